// round 1
// baseline (speedup 1.0000x reference)
#include <cuda_runtime.h>
#include <cstdint>
#include <math.h>

#define NLEV 24
#define CAPACITY (1u << 18)
#define BLOCK 128

__device__ __forceinline__ float gelu_exact(float v) {
    return 0.5f * v * (1.0f + erff(v * 0.70710678118654752f));
}

__global__ __launch_bounds__(BLOCK)
void sdf_kernel(const float* __restrict__ points,
                const int*   __restrict__ iter_nr,
                const float* __restrict__ tables,
                const float* __restrict__ shifts,
                const float* __restrict__ w1, const float* __restrict__ b1,
                const float* __restrict__ w2, const float* __restrict__ b2,
                const float* __restrict__ w3, const float* __restrict__ b3,
                const float* __restrict__ w4, const float* __restrict__ b4,
                float* __restrict__ out, int N)
{
    __shared__ float s_w1[51 * 32];
    __shared__ float s_b1[32];
    __shared__ float s_w2[32 * 32];
    __shared__ float s_b2[32];
    __shared__ float s_w3[32 * 32];
    __shared__ float s_b3[32];
    __shared__ float s_w4[32 * 36];      // padded rows (33 valid + 3 pad)
    __shared__ float s_b4[33];
    __shared__ float s_shift[NLEV * 3];
    __shared__ float s_scale[NLEV];
    __shared__ float s_win[NLEV];
    __shared__ float s_stage[BLOCK * 33]; // geom staging, stride 33 (conflict-free)

    const int tid = threadIdx.x;

    // ---- cooperative shared load of weights / constants ----
    for (int i = tid; i < 51 * 32; i += BLOCK) s_w1[i] = w1[i];
    for (int i = tid; i < 32 * 32; i += BLOCK) s_w2[i] = w2[i];
    for (int i = tid; i < 32 * 32; i += BLOCK) s_w3[i] = w3[i];
    for (int i = tid; i < 32 * 36; i += BLOCK) {
        int r = i / 36, c = i - r * 36;
        s_w4[i] = (c < 33) ? w4[r * 33 + c] : 0.0f;
    }
    if (tid < 32) { s_b1[tid] = b1[tid]; s_b2[tid] = b2[tid]; s_b3[tid] = b3[tid]; }
    if (tid < 33) s_b4[tid] = b4[tid];
    if (tid < NLEV * 3) s_shift[tid] = shifts[tid];
    if (tid < NLEV) {
        // SCALES = geomspace(1, 1e-4, 24) = 10^(i * (-4/23)) computed in float64
        double step = -4.0 / 23.0;
        s_scale[tid] = (float)pow(10.0, step * (double)tid);
        // coarse-to-fine window
        float t = fminf(fmaxf((float)iter_nr[0] / 10000.0f, 0.0f), 1.0f);
        float alpha = (0.3f + 0.7f * t) * (float)NLEV;
        float x = fminf(fmaxf(alpha - (float)tid, 0.0f), 1.0f);
        s_win[tid] = 0.5f * (1.0f - cosf(3.14159265358979323846f * x));
    }
    __syncthreads();

    const int n = blockIdx.x * BLOCK + tid;
    const bool active = (n < N);

    float acc[33]; // final layer accumulators (also carries output)

    if (active) {
        const float p0 = points[n * 3 + 0];
        const float p1 = points[n * 3 + 1];
        const float p2 = points[n * 3 + 2];

        // SF[i] = 4*sqrt(2/3)/sqrt((i+1)(i+2))
        const float SF0 = 2.30940107675850341796875f;   // float(2.3094010767585034)
        const float SF1 = 1.33333333333333333f;
        const float SF2 = 0.94280904158206336f;

        // ---- layer-1 accumulator, seeded with bias + point*0.001 rows (48..50)
        float h1[32];
        {
            const float x48 = p0 * 0.001f, x49 = p1 * 0.001f, x50 = p2 * 0.001f;
            const float4* wa = (const float4*)(s_w1 + 48 * 32);
            const float4* wb = (const float4*)(s_w1 + 49 * 32);
            const float4* wc = (const float4*)(s_w1 + 50 * 32);
            const float4* bb = (const float4*)s_b1;
            #pragma unroll
            for (int q = 0; q < 8; q++) {
                float4 a = wa[q], b = wb[q], c = wc[q], bv = bb[q];
                h1[4*q+0] = bv.x + x48*a.x + x49*b.x + x50*c.x;
                h1[4*q+1] = bv.y + x48*a.y + x49*b.y + x50*c.y;
                h1[4*q+2] = bv.z + x48*a.z + x49*b.z + x50*c.z;
                h1[4*q+3] = bv.w + x48*a.w + x49*b.w + x50*c.w;
            }
        }

        // ---- permutohedral encoding, accumulated straight into h1 ----
        #pragma unroll 1
        for (int lev = 0; lev < NLEV; ++lev) {
            const float wl = s_win[lev];
            if (wl == 0.0f) continue;  // window==0 -> feature is exactly 0

            const float sc = s_scale[lev];
            const float pos0 = p0 / sc + s_shift[lev * 3 + 0];
            const float pos1 = p1 / sc + s_shift[lev * 3 + 1];
            const float pos2 = p2 / sc + s_shift[lev * 3 + 2];
            const float cf0 = pos0 * SF0, cf1 = pos1 * SF1, cf2 = pos2 * SF2;

            // suffix cumsum order of reference: S2=cf2, S1=cf2+cf1, S0=S1+cf0
            const float S2 = cf2;
            const float S1 = cf2 + cf1;
            const float S0 = S1 + cf0;

            float e[4];
            e[0] = S0;
            e[1] = S1 - cf0;
            e[2] = S2 - 2.0f * cf1;
            e[3] = -3.0f * cf2;

            float r[4];
            #pragma unroll
            for (int i = 0; i < 4; i++) r[i] = rintf(e[i] * 0.25f) * 4.0f;

            const int sumv = (int)rintf((r[0] + r[1] + r[2] + r[3]) * 0.25f);

            float d[4];
            #pragma unroll
            for (int i = 0; i < 4; i++) d[i] = e[i] - r[i];

            // rank = stable argsort(argsort(-diff)) + sum_
            int rk[4];
            #pragma unroll
            for (int i = 0; i < 4; i++) {
                int c = sumv;
                #pragma unroll
                for (int j = 0; j < 4; j++)
                    c += (d[j] > d[i] || (d[j] == d[i] && j < i)) ? 1 : 0;
                rk[i] = c;
            }
            #pragma unroll
            for (int i = 0; i < 4; i++) {
                if (rk[i] < 0)      { rk[i] += 4; r[i] += 4.0f; }
                else if (rk[i] > 3) { rk[i] -= 4; r[i] -= 4.0f; }
            }

            float del[4];
            #pragma unroll
            for (int i = 0; i < 4; i++) del[i] = (e[i] - r[i]) * 0.25f;

            // barycentric weights
            float bq0 = 0.f, bq1 = 0.f, bq2 = 0.f, bq3 = 0.f, bq4 = 0.f;
            #pragma unroll
            for (int i = 0; i < 4; i++) {
                const int id = 3 - rk[i];
                const float dv = del[i];
                if (id == 0)      { bq0 += dv; bq1 -= dv; }
                else if (id == 1) { bq1 += dv; bq2 -= dv; }
                else if (id == 2) { bq2 += dv; bq3 -= dv; }
                else              { bq3 += dv; bq4 -= dv; }
            }
            float wgt[4];
            wgt[0] = bq0 + (1.0f + bq4);
            wgt[1] = bq1;
            wgt[2] = bq2;
            wgt[3] = bq3;

            const int c0 = (int)r[0], c1 = (int)r[1], c2 = (int)r[2];
            const float2* tab = (const float2*)tables + (size_t)lev * CAPACITY;

            float f0 = 0.0f, f1 = 0.0f;
            #pragma unroll
            for (int k = 0; k < 4; k++) {
                const uint32_t k0 = (uint32_t)(c0 + k - ((rk[0] > 3 - k) ? 4 : 0));
                const uint32_t k1 = (uint32_t)(c1 + k - ((rk[1] > 3 - k) ? 4 : 0));
                const uint32_t k2 = (uint32_t)(c2 + k - ((rk[2] > 3 - k) ? 4 : 0));
                const uint32_t h = k0 ^ (k1 * 2654435761u) ^ (k2 * 805459861u);
                const uint32_t idx = h & (CAPACITY - 1u);
                const float2 g = __ldg(tab + idx);
                f0 = fmaf(g.x, wgt[k], f0);
                f1 = fmaf(g.y, wgt[k], f1);
            }
            f0 *= wl; f1 *= wl;

            // accumulate into layer-1 hidden: rows 2*lev and 2*lev+1 of w1
            const float4* wr = (const float4*)(s_w1 + lev * 64);
            #pragma unroll
            for (int q = 0; q < 8; q++) {
                float4 a = wr[q], b = wr[q + 8];
                h1[4*q+0] += f0 * a.x + f1 * b.x;
                h1[4*q+1] += f0 * a.y + f1 * b.y;
                h1[4*q+2] += f0 * a.z + f1 * b.z;
                h1[4*q+3] += f0 * a.w + f1 * b.w;
            }
        }

        // ---- MLP ----
        #pragma unroll
        for (int o = 0; o < 32; o++) h1[o] = gelu_exact(h1[o]);

        float h2[32];
        {
            const float4* bb = (const float4*)s_b2;
            #pragma unroll
            for (int q = 0; q < 8; q++) {
                float4 bv = bb[q];
                h2[4*q+0] = bv.x; h2[4*q+1] = bv.y; h2[4*q+2] = bv.z; h2[4*q+3] = bv.w;
            }
        }
        #pragma unroll
        for (int i = 0; i < 32; i++) {
            const float xi = h1[i];
            const float4* wr = (const float4*)(s_w2 + i * 32);
            #pragma unroll
            for (int q = 0; q < 8; q++) {
                float4 a = wr[q];
                h2[4*q+0] = fmaf(xi, a.x, h2[4*q+0]);
                h2[4*q+1] = fmaf(xi, a.y, h2[4*q+1]);
                h2[4*q+2] = fmaf(xi, a.z, h2[4*q+2]);
                h2[4*q+3] = fmaf(xi, a.w, h2[4*q+3]);
            }
        }
        #pragma unroll
        for (int o = 0; o < 32; o++) h2[o] = gelu_exact(h2[o]);

        // layer 3 back into h1
        {
            const float4* bb = (const float4*)s_b3;
            #pragma unroll
            for (int q = 0; q < 8; q++) {
                float4 bv = bb[q];
                h1[4*q+0] = bv.x; h1[4*q+1] = bv.y; h1[4*q+2] = bv.z; h1[4*q+3] = bv.w;
            }
        }
        #pragma unroll
        for (int i = 0; i < 32; i++) {
            const float xi = h2[i];
            const float4* wr = (const float4*)(s_w3 + i * 32);
            #pragma unroll
            for (int q = 0; q < 8; q++) {
                float4 a = wr[q];
                h1[4*q+0] = fmaf(xi, a.x, h1[4*q+0]);
                h1[4*q+1] = fmaf(xi, a.y, h1[4*q+1]);
                h1[4*q+2] = fmaf(xi, a.z, h1[4*q+2]);
                h1[4*q+3] = fmaf(xi, a.w, h1[4*q+3]);
            }
        }
        #pragma unroll
        for (int o = 0; o < 32; o++) h1[o] = gelu_exact(h1[o]);

        // layer 4 -> acc[33]
        #pragma unroll
        for (int j = 0; j < 33; j++) acc[j] = s_b4[j];
        #pragma unroll
        for (int i = 0; i < 32; i++) {
            const float xi = h1[i];
            const float* wr = s_w4 + i * 36;
            #pragma unroll
            for (int q = 0; q < 8; q++) {
                float4 a = *(const float4*)(wr + 4 * q);
                acc[4*q+0] = fmaf(xi, a.x, acc[4*q+0]);
                acc[4*q+1] = fmaf(xi, a.y, acc[4*q+1]);
                acc[4*q+2] = fmaf(xi, a.z, acc[4*q+2]);
                acc[4*q+3] = fmaf(xi, a.w, acc[4*q+3]);
            }
            acc[32] = fmaf(xi, wr[32], acc[32]);
        }

        // sdf (coalesced across warp)
        out[n] = acc[0];

        // stage geom (acc[1..32]) in smem for coalesced write
        #pragma unroll
        for (int j = 0; j < 32; j++) s_stage[tid * 33 + j] = acc[1 + j];
    }

    __syncthreads();

    // coalesced geom writeback: rows [blockBase .. blockBase+nvalid) of width 32
    const int blockBase = blockIdx.x * BLOCK;
    int nvalid = N - blockBase;
    if (nvalid > BLOCK) nvalid = BLOCK;
    if (nvalid > 0) {
        float* gout = out + (size_t)N + (size_t)blockBase * 32;
        for (int i = tid; i < nvalid * 32; i += BLOCK) {
            const int row = i >> 5;
            const int col = i & 31;
            gout[i] = s_stage[row * 33 + col];
        }
    }
}

extern "C" void kernel_launch(void* const* d_in, const int* in_sizes, int n_in,
                              void* d_out, int out_size)
{
    const float* points = (const float*)d_in[0];
    const int*   iter   = (const int*)  d_in[1];
    const float* tables = (const float*)d_in[2];
    const float* shifts = (const float*)d_in[3];
    const float* w1 = (const float*)d_in[4];  const float* b1 = (const float*)d_in[5];
    const float* w2 = (const float*)d_in[6];  const float* b2 = (const float*)d_in[7];
    const float* w3 = (const float*)d_in[8];  const float* b3 = (const float*)d_in[9];
    const float* w4 = (const float*)d_in[10]; const float* b4 = (const float*)d_in[11];

    const int N = in_sizes[0] / 3;
    const int grid = (N + BLOCK - 1) / BLOCK;
    sdf_kernel<<<grid, BLOCK>>>(points, iter, tables, shifts,
                                w1, b1, w2, b2, w3, b3, w4, b4,
                                (float*)d_out, N);
}

// round 2
// speedup vs baseline: 1.2185x; 1.2185x over previous
#include <cuda_runtime.h>
#include <cstdint>
#include <math.h>

#define NLEV 24
#define CAPACITY (1u << 18)
#define BLOCK 128

__device__ __forceinline__ float gelu_exact(float v) {
    return 0.5f * v * (1.0f + erff(v * 0.70710678118654752f));
}

union F2U { float2 f; unsigned long long u; };

// Packed dual-lane FMA: d = a*b + c on both f32 lanes (Blackwell FFMA2).
__device__ __forceinline__ float2 ffma2(float2 a, float2 b, float2 c) {
    F2U A, B, C, D;
    A.f = a; B.f = b; C.f = c;
    asm("fma.rn.f32x2 %0, %1, %2, %3;" : "=l"(D.u) : "l"(A.u), "l"(B.u), "l"(C.u));
    return D.f;
}

__global__ __launch_bounds__(BLOCK)
void sdf_kernel(const float* __restrict__ points,
                const int*   __restrict__ iter_nr,
                const float* __restrict__ tables,
                const float* __restrict__ shifts,
                const float* __restrict__ w1, const float* __restrict__ b1,
                const float* __restrict__ w2, const float* __restrict__ b2,
                const float* __restrict__ w3, const float* __restrict__ b3,
                const float* __restrict__ w4, const float* __restrict__ b4,
                float* __restrict__ out, int N)
{
    __shared__ float2 s_w1[51 * 16];
    __shared__ float2 s_b1[16];
    __shared__ float2 s_w2[32 * 16];
    __shared__ float2 s_b2[16];
    __shared__ float2 s_w3[32 * 16];
    __shared__ float2 s_b3[16];
    __shared__ float  s_w4g[32 * 32];   // geom columns 1..32, row stride 32
    __shared__ float  s_w4s[32];        // sdf column 0
    __shared__ float  s_b4[33];
    __shared__ float  s_shift[NLEV * 3];
    __shared__ float  s_invsc[NLEV];
    __shared__ float  s_win[NLEV];
    __shared__ int    s_nlev;
    __shared__ float  s_stage[BLOCK * 33]; // geom staging (stride 33: conflict-free)

    const int tid = threadIdx.x;

    // ---- cooperative shared load of weights / constants ----
    {
        const float2* g1 = (const float2*)w1;
        const float2* g2 = (const float2*)w2;
        const float2* g3 = (const float2*)w3;
        for (int i = tid; i < 51 * 16; i += BLOCK) s_w1[i] = g1[i];
        for (int i = tid; i < 32 * 16; i += BLOCK) s_w2[i] = g2[i];
        for (int i = tid; i < 32 * 16; i += BLOCK) s_w3[i] = g3[i];
    }
    for (int i = tid; i < 32 * 33; i += BLOCK) {
        int r = i / 33, c = i - r * 33;
        float v = w4[i];
        if (c == 0) s_w4s[r] = v; else s_w4g[r * 32 + (c - 1)] = v;
    }
    if (tid < 16) {
        s_b1[tid] = ((const float2*)b1)[tid];
        s_b2[tid] = ((const float2*)b2)[tid];
        s_b3[tid] = ((const float2*)b3)[tid];
    }
    if (tid < 33) s_b4[tid] = b4[tid];
    if (tid < NLEV * 3) s_shift[tid] = shifts[tid];
    if (tid < NLEV) {
        // SCALES = geomspace(1, 1e-4, 24) = 10^(i * (-4/23)) in float64 -> f32
        double step = -4.0 / 23.0;
        float sc = (float)pow(10.0, step * (double)tid);
        s_invsc[tid] = 1.0f / sc;
        float t = fminf(fmaxf((float)iter_nr[0] / 10000.0f, 0.0f), 1.0f);
        float alpha = (0.3f + 0.7f * t) * (float)NLEV;
        float x = fminf(fmaxf(alpha - (float)tid, 0.0f), 1.0f);
        s_win[tid] = 0.5f * (1.0f - cosf(3.14159265358979323846f * x));
        if (tid == 0) {
            int na = (int)ceilf(alpha);
            if (na > NLEV) na = NLEV;
            if (na < 0) na = 0;
            s_nlev = na;
        }
    }
    __syncthreads();

    const int n = blockIdx.x * BLOCK + tid;
    const bool active = (n < N);
    const int nlev = s_nlev;

    float  acc0;        // sdf
    float2 accg[16];    // geom 1..32

    if (active) {
        const float p0 = points[n * 3 + 0];
        const float p1 = points[n * 3 + 1];
        const float p2 = points[n * 3 + 2];

        // SF[i] = 4*sqrt(2/3)/sqrt((i+1)(i+2))
        const float SF0 = 2.30940107675850341796875f;
        const float SF1 = 1.33333333333333333f;
        const float SF2 = 0.94280904158206336f;

        // ---- layer-1 accumulator, seeded with bias + point*0.001 rows (48..50)
        float2 h1[16];
        {
            const float2 xa = make_float2(p0 * 0.001f, p0 * 0.001f);
            const float2 xb = make_float2(p1 * 0.001f, p1 * 0.001f);
            const float2 xc = make_float2(p2 * 0.001f, p2 * 0.001f);
            const float2* wa = s_w1 + 48 * 16;
            const float2* wb = s_w1 + 49 * 16;
            const float2* wc = s_w1 + 50 * 16;
            #pragma unroll
            for (int q = 0; q < 16; q++) {
                float2 v = ffma2(xa, wa[q], s_b1[q]);
                v = ffma2(xb, wb[q], v);
                h1[q] = ffma2(xc, wc[q], v);
            }
        }

        // ---- permutohedral encoding, accumulated straight into h1 ----
        #pragma unroll 1
        for (int lev = 0; lev < nlev; ++lev) {
            const float inv = s_invsc[lev];
            const float pos0 = fmaf(p0, inv, s_shift[lev * 3 + 0]);
            const float pos1 = fmaf(p1, inv, s_shift[lev * 3 + 1]);
            const float pos2 = fmaf(p2, inv, s_shift[lev * 3 + 2]);
            const float cf0 = pos0 * SF0, cf1 = pos1 * SF1, cf2 = pos2 * SF2;

            const float S2 = cf2;
            const float S1 = cf2 + cf1;
            const float S0 = S1 + cf0;

            float e[4];
            e[0] = S0;
            e[1] = S1 - cf0;
            e[2] = S2 - 2.0f * cf1;
            e[3] = -3.0f * cf2;

            float r[4];
            #pragma unroll
            for (int i = 0; i < 4; i++) r[i] = rintf(e[i] * 0.25f) * 4.0f;

            const int sumv = (int)rintf((r[0] + r[1] + r[2] + r[3]) * 0.25f);

            float d[4];
            #pragma unroll
            for (int i = 0; i < 4; i++) d[i] = e[i] - r[i];

            // rank = stable argsort(argsort(-diff)) + sum_
            int rk[4];
            #pragma unroll
            for (int i = 0; i < 4; i++) {
                int c = sumv;
                #pragma unroll
                for (int j = 0; j < 4; j++)
                    c += (d[j] > d[i] || (d[j] == d[i] && j < i)) ? 1 : 0;
                rk[i] = c;
            }
            #pragma unroll
            for (int i = 0; i < 4; i++) {
                if (rk[i] < 0)      { rk[i] += 4; r[i] += 4.0f; }
                else if (rk[i] > 3) { rk[i] -= 4; r[i] -= 4.0f; }
            }

            float del[4];
            #pragma unroll
            for (int i = 0; i < 4; i++) del[i] = (e[i] - r[i]) * 0.25f;

            // barycentric weights
            float bq0 = 0.f, bq1 = 0.f, bq2 = 0.f, bq3 = 0.f, bq4 = 0.f;
            #pragma unroll
            for (int i = 0; i < 4; i++) {
                const int id = 3 - rk[i];
                const float dv = del[i];
                if (id == 0)      { bq0 += dv; bq1 -= dv; }
                else if (id == 1) { bq1 += dv; bq2 -= dv; }
                else if (id == 2) { bq2 += dv; bq3 -= dv; }
                else              { bq3 += dv; bq4 -= dv; }
            }
            float wgt[4];
            wgt[0] = bq0 + (1.0f + bq4);
            wgt[1] = bq1;
            wgt[2] = bq2;
            wgt[3] = bq3;

            const int c0 = (int)r[0], c1 = (int)r[1], c2 = (int)r[2];
            const float2* tab = (const float2*)tables + (size_t)lev * CAPACITY;

            float2 fe = make_float2(0.0f, 0.0f);
            #pragma unroll
            for (int k = 0; k < 4; k++) {
                const uint32_t k0 = (uint32_t)(c0 + k - ((rk[0] > 3 - k) ? 4 : 0));
                const uint32_t k1 = (uint32_t)(c1 + k - ((rk[1] > 3 - k) ? 4 : 0));
                const uint32_t k2 = (uint32_t)(c2 + k - ((rk[2] > 3 - k) ? 4 : 0));
                const uint32_t h = k0 ^ (k1 * 2654435761u) ^ (k2 * 805459861u);
                const uint32_t idx = h & (CAPACITY - 1u);
                const float2 g = __ldg(tab + idx);
                fe = ffma2(make_float2(wgt[k], wgt[k]), g, fe);
            }
            const float wl = s_win[lev];
            const float2 f02 = make_float2(fe.x * wl, fe.x * wl);
            const float2 f12 = make_float2(fe.y * wl, fe.y * wl);

            // accumulate into layer-1 hidden: rows 2*lev, 2*lev+1 of w1
            const float2* ra = s_w1 + (2 * lev) * 16;
            const float2* rb = ra + 16;
            #pragma unroll
            for (int q = 0; q < 16; q++) {
                float2 v = ffma2(f02, ra[q], h1[q]);
                h1[q] = ffma2(f12, rb[q], v);
            }
        }

        // ---- MLP ----
        #pragma unroll
        for (int q = 0; q < 16; q++) {
            h1[q].x = gelu_exact(h1[q].x);
            h1[q].y = gelu_exact(h1[q].y);
        }

        float2 h2[16];
        #pragma unroll
        for (int q = 0; q < 16; q++) h2[q] = s_b2[q];
        #pragma unroll
        for (int i = 0; i < 16; i++) {
            const float2 xi = h1[i];
            const float2 xa = make_float2(xi.x, xi.x);
            const float2 xb = make_float2(xi.y, xi.y);
            const float2* wr0 = s_w2 + (2 * i) * 16;
            const float2* wr1 = wr0 + 16;
            #pragma unroll
            for (int q = 0; q < 16; q++) {
                float2 v = ffma2(xa, wr0[q], h2[q]);
                h2[q] = ffma2(xb, wr1[q], v);
            }
        }
        #pragma unroll
        for (int q = 0; q < 16; q++) {
            h2[q].x = gelu_exact(h2[q].x);
            h2[q].y = gelu_exact(h2[q].y);
        }

        // layer 3 back into h1
        #pragma unroll
        for (int q = 0; q < 16; q++) h1[q] = s_b3[q];
        #pragma unroll
        for (int i = 0; i < 16; i++) {
            const float2 xi = h2[i];
            const float2 xa = make_float2(xi.x, xi.x);
            const float2 xb = make_float2(xi.y, xi.y);
            const float2* wr0 = s_w3 + (2 * i) * 16;
            const float2* wr1 = wr0 + 16;
            #pragma unroll
            for (int q = 0; q < 16; q++) {
                float2 v = ffma2(xa, wr0[q], h1[q]);
                h1[q] = ffma2(xb, wr1[q], v);
            }
        }
        #pragma unroll
        for (int q = 0; q < 16; q++) {
            h1[q].x = gelu_exact(h1[q].x);
            h1[q].y = gelu_exact(h1[q].y);
        }

        // layer 4
        acc0 = s_b4[0];
        #pragma unroll
        for (int q = 0; q < 16; q++)
            accg[q] = make_float2(s_b4[1 + 2 * q], s_b4[2 + 2 * q]);
        #pragma unroll
        for (int i = 0; i < 16; i++) {
            const float x0 = h1[i].x, x1 = h1[i].y;
            const float2 xa = make_float2(x0, x0);
            const float2 xb = make_float2(x1, x1);
            const float2* wr0 = (const float2*)(s_w4g + (2 * i) * 32);
            const float2* wr1 = (const float2*)(s_w4g + (2 * i + 1) * 32);
            acc0 = fmaf(x0, s_w4s[2 * i], acc0);
            acc0 = fmaf(x1, s_w4s[2 * i + 1], acc0);
            #pragma unroll
            for (int q = 0; q < 16; q++) {
                float2 v = ffma2(xa, wr0[q], accg[q]);
                accg[q] = ffma2(xb, wr1[q], v);
            }
        }

        // sdf (coalesced across warp)
        out[n] = acc0;

        // stage geom in smem for coalesced write (stride 33, conflict-free)
        #pragma unroll
        for (int q = 0; q < 16; q++) {
            s_stage[tid * 33 + 2 * q]     = accg[q].x;
            s_stage[tid * 33 + 2 * q + 1] = accg[q].y;
        }
    }

    __syncthreads();

    // coalesced geom writeback
    const int blockBase = blockIdx.x * BLOCK;
    int nvalid = N - blockBase;
    if (nvalid > BLOCK) nvalid = BLOCK;
    if (nvalid > 0) {
        float* gout = out + (size_t)N + (size_t)blockBase * 32;
        for (int i = tid; i < nvalid * 32; i += BLOCK) {
            const int row = i >> 5;
            const int col = i & 31;
            gout[i] = s_stage[row * 33 + col];
        }
    }
}

extern "C" void kernel_launch(void* const* d_in, const int* in_sizes, int n_in,
                              void* d_out, int out_size)
{
    const float* points = (const float*)d_in[0];
    const int*   iter   = (const int*)  d_in[1];
    const float* tables = (const float*)d_in[2];
    const float* shifts = (const float*)d_in[3];
    const float* w1 = (const float*)d_in[4];  const float* b1 = (const float*)d_in[5];
    const float* w2 = (const float*)d_in[6];  const float* b2 = (const float*)d_in[7];
    const float* w3 = (const float*)d_in[8];  const float* b3 = (const float*)d_in[9];
    const float* w4 = (const float*)d_in[10]; const float* b4 = (const float*)d_in[11];

    const int N = in_sizes[0] / 3;
    const int grid = (N + BLOCK - 1) / BLOCK;
    sdf_kernel<<<grid, BLOCK>>>(points, iter, tables, shifts,
                                w1, b1, w2, b2, w3, b3, w4, b4,
                                (float*)d_out, N);
}